// round 3
// baseline (speedup 1.0000x reference)
#include <cuda_runtime.h>

// GaussianSampler: R[b,c] = sum_{y,x} X[b,c,y,x] * gx[c,x] * gy[c,y] / norm
// R3: per-thread weight computation. For thread t, x-position of its float4
// is iteration-invariant ((4t)&63) and y walks 4 values ((4t>>6)+16k). So each
// thread computes its own 8 Gaussian weights via __expf — no smem weight
// tables, no prologue barrier. The 4 LDG.128s issue FIRST and the MUFU work
// hides under their 577-cycle DRAM latency.

#define NCH 1024
#define HH  64
#define WW  64

__global__ __launch_bounds__(256)
void gaussian_sampler_kernel(
    const float* __restrict__ X,     // [B, C, H, W]
    const float* __restrict__ wx,    // [C]
    const float* __restrict__ wy,    // [C]
    const float* __restrict__ wsx,   // [C]
    const float* __restrict__ wsy,   // [C]
    float* __restrict__ out)         // [B, C]
{
    const int blk = blockIdx.x;          // = b*NCH + c
    const int c   = blk & (NCH - 1);
    const int t   = threadIdx.x;

    // ---- issue the 4 independent LDG.128s first (front-batched) ----
    const float4* __restrict__ xp =
        reinterpret_cast<const float4*>(X + (size_t)blk * (HH * WW));
    float4 v0 = xp[t];
    float4 v1 = xp[t + 256];
    float4 v2 = xp[t + 512];
    float4 v3 = xp[t + 768];

    // ---- per-thread weights (overlap with loads in flight) ----
    // coord[i] = -0.984375 + i/32
    const int x  = (4 * t) & 63;         // iteration-invariant column
    const int y0 = (4 * t) >> 6;         // 0..15; rows y0 + 16k

    float mx = wx[c], my = wy[c];
    float sx = wsx[c], sy = wsy[c];
    float ax = -0.5f / (sx * sx);        // exp(ax * d^2)
    float ay = -0.5f / (sy * sy);

    float cx = -0.984375f + (float)x * 0.03125f;
    float dx0 = cx - mx;
    float dx1 = dx0 + 0.03125f;
    float dx2 = dx0 + 0.0625f;
    float dx3 = dx0 + 0.09375f;
    float gx0 = __expf(ax * dx0 * dx0);
    float gx1 = __expf(ax * dx1 * dx1);
    float gx2 = __expf(ax * dx2 * dx2);
    float gx3 = __expf(ax * dx3 * dx3);

    float cy = -0.984375f + (float)y0 * 0.03125f;
    float dy0 = cy - my;
    float dy1 = dy0 + 0.5f;              // +16 rows
    float dy2 = dy0 + 1.0f;
    float dy3 = dy0 + 1.5f;
    float gy0 = __expf(ay * dy0 * dy0);
    float gy1 = __expf(ay * dy1 * dy1);
    float gy2 = __expf(ay * dy2 * dy2);
    float gy3 = __expf(ay * dy3 * dy3);

    // ---- dot products ----
    float acc;
    acc  = gy0 * (v0.x * gx0 + v0.y * gx1 + v0.z * gx2 + v0.w * gx3);
    acc += gy1 * (v1.x * gx0 + v1.y * gx1 + v1.z * gx2 + v1.w * gx3);
    acc += gy2 * (v2.x * gx0 + v2.y * gx1 + v2.z * gx2 + v2.w * gx3);
    acc += gy3 * (v3.x * gx0 + v3.y * gx1 + v3.z * gx2 + v3.w * gx3);

    // ---- reduction ----
    #pragma unroll
    for (int off = 16; off > 0; off >>= 1)
        acc += __shfl_down_sync(0xffffffffu, acc, off);

    __shared__ float red[8];
    if ((t & 31) == 0) red[t >> 5] = acc;
    __syncthreads();

    if (t < 8) {
        float v = red[t];
        #pragma unroll
        for (int off = 4; off > 0; off >>= 1)
            v += __shfl_down_sync(0x000000ffu, v, off);
        if (t == 0) {
            // 1 / (sqrt(2*pi) * sx * sy * H*W/4), H*W/4 = 1024
            float scale = 1.0f / (2.5066282746310002f * sx * sy * 1024.0f);
            out[blk] = v * scale;
        }
    }
}

extern "C" void kernel_launch(void* const* d_in, const int* in_sizes, int n_in,
                              void* d_out, int out_size) {
    // metadata order: X, wx, wy, wsigmax, wsigmay, mask
    const float* X   = (const float*)d_in[0];
    const float* wx  = (const float*)d_in[1];
    const float* wy  = (const float*)d_in[2];
    const float* wsx = (const float*)d_in[3];
    const float* wsy = (const float*)d_in[4];
    // mask (d_in[5]) is all-true by construction; nonzero(size=C) gather is identity.
    float* out = (float*)d_out;

    const int B = in_sizes[0] / (NCH * HH * WW);   // 32
    const int nblocks = B * NCH;                   // 32768

    gaussian_sampler_kernel<<<nblocks, 256>>>(X, wx, wy, wsx, wsy, out);
}

// round 4
// speedup vs baseline: 1.0230x; 1.0230x over previous
#include <cuda_runtime.h>

// GaussianSampler: R[b,c] = sum_{y,x} X[b,c,y,x] * gx[c,x] * gy[c,y] / norm
// R4 = R1 (best: 77.4us, occ 91%, 30 regs) + L2 prefetch of the whole 16 KiB
// tile at block entry (zero register cost) so DRAM traffic starts during the
// expf/barrier prologue, + norm scale folded into gy.

#define NCH 1024
#define HH  64
#define WW  64

__global__ __launch_bounds__(256, 8)
void gaussian_sampler_kernel(
    const float* __restrict__ X,     // [B, C, H, W]
    const float* __restrict__ wx,    // [C]
    const float* __restrict__ wy,    // [C]
    const float* __restrict__ wsx,   // [C]
    const float* __restrict__ wsy,   // [C]
    float* __restrict__ out)         // [B, C]
{
    const int blk = blockIdx.x;          // = b*NCH + c
    const int c   = blk & (NCH - 1);
    const int t   = threadIdx.x;

    const float* tile = X + (size_t)blk * (HH * WW);

    // ---- fire DRAM->L2 prefetch for the whole tile first (no reg cost) ----
    // 16 KiB = 128 lines of 128 B; threads 0..127 take one line each.
    if (t < 128) {
        const float* p = tile + t * 32;  // 32 floats = 128 B
        asm volatile("prefetch.global.L2 [%0];" :: "l"(p));
    }

    __shared__ float gx[WW];
    __shared__ float gy[HH];             // norm scale folded in
    __shared__ float red[8];

    // coord[i] = linspace(-63/64, 63/64, 64)[i] = -0.984375 + i/32
    if (t < 64) {
        float s = wsx[c];
        float d = (-0.984375f + (float)t * 0.03125f) - wx[c];
        gx[t] = __expf(-d * d / (2.0f * s * s));
    } else if (t < 128) {
        int i = t - 64;
        float sy = wsy[c];
        float sx = wsx[c];
        float d = (-0.984375f + (float)i * 0.03125f) - wy[c];
        // fold 1/(sqrt(2pi)*sx*sy*1024) into gy
        float scale = 1.0f / (2.5066282746310002f * sx * sy * 1024.0f);
        gy[i] = __expf(-d * d / (2.0f * sy * sy)) * scale;
    }
    __syncthreads();

    const float4* __restrict__ xp = reinterpret_cast<const float4*>(tile);

    float acc = 0.0f;
    #pragma unroll
    for (int it = 0; it < 4; it++) {
        int j = t + it * 256;            // float4 index in [0, 1024)
        float4 v = xp[j];
        int lin = j << 2;
        int y = lin >> 6;
        int x = lin & 63;
        float gyv = gy[y];
        acc += gyv * (v.x * gx[x] + v.y * gx[x + 1] +
                      v.z * gx[x + 2] + v.w * gx[x + 3]);
    }

    // Intra-warp reduce
    #pragma unroll
    for (int off = 16; off > 0; off >>= 1)
        acc += __shfl_down_sync(0xffffffffu, acc, off);

    if ((t & 31) == 0) red[t >> 5] = acc;
    __syncthreads();

    if (t < 8) {
        float v = red[t];
        #pragma unroll
        for (int off = 4; off > 0; off >>= 1)
            v += __shfl_down_sync(0x000000ffu, v, off);
        if (t == 0) out[blk] = v;
    }
}

extern "C" void kernel_launch(void* const* d_in, const int* in_sizes, int n_in,
                              void* d_out, int out_size) {
    // metadata order: X, wx, wy, wsigmax, wsigmay, mask
    const float* X   = (const float*)d_in[0];
    const float* wx  = (const float*)d_in[1];
    const float* wy  = (const float*)d_in[2];
    const float* wsx = (const float*)d_in[3];
    const float* wsy = (const float*)d_in[4];
    // mask (d_in[5]) is all-true by construction; nonzero(size=C) gather is identity.
    float* out = (float*)d_out;

    const int B = in_sizes[0] / (NCH * HH * WW);   // 32
    const int nblocks = B * NCH;                   // 32768

    gaussian_sampler_kernel<<<nblocks, 256>>>(X, wx, wy, wsx, wsy, out);
}

// round 5
// speedup vs baseline: 1.0264x; 1.0033x over previous
#include <cuda_runtime.h>

// GaussianSampler: R[b,c] = sum_{y,x} X[b,c,y,x] * gx[c,x] * gy[c,y] / norm
// R5 = R1 smem-weight prologue + restructured body: all 4 LDG.128s issued
// back-to-back FIRST (true MLP=4), then weights fetched via one aligned
// LDS.128 (gx, iteration-invariant per thread) + 4 scalar LDS (gy).
// __launch_bounds__(256,8) pins regs<=32 so occupancy stays at 8 CTAs/SM.

#define NCH 1024
#define HH  64
#define WW  64

__global__ __launch_bounds__(256, 8)
void gaussian_sampler_kernel(
    const float* __restrict__ X,     // [B, C, H, W]
    const float* __restrict__ wx,    // [C]
    const float* __restrict__ wy,    // [C]
    const float* __restrict__ wsx,   // [C]
    const float* __restrict__ wsy,   // [C]
    float* __restrict__ out)         // [B, C]
{
    const int blk = blockIdx.x;          // = b*NCH + c
    const int c   = blk & (NCH - 1);
    const int t   = threadIdx.x;

    __shared__ float gx[WW];             // x-direction Gaussian
    __shared__ float gy[HH];             // y-direction Gaussian, norm folded in
    __shared__ float red[8];

    // coord[i] = linspace(-63/64, 63/64, 64)[i] = -0.984375 + i/32
    if (t < 64) {
        float s = wsx[c];
        float d = (-0.984375f + (float)t * 0.03125f) - wx[c];
        gx[t] = __expf(-d * d / (2.0f * s * s));
    } else if (t < 128) {
        int i = t - 64;
        float sy = wsy[c];
        float sx = wsx[c];
        float d = (-0.984375f + (float)i * 0.03125f) - wy[c];
        // fold 1/(sqrt(2pi)*sx*sy*1024) into gy
        float scale = 1.0f / (2.5066282746310002f * sx * sy * 1024.0f);
        gy[i] = __expf(-d * d / (2.0f * sy * sy)) * scale;
    }
    __syncthreads();

    const float4* __restrict__ xp =
        reinterpret_cast<const float4*>(X + (size_t)blk * (HH * WW));

    // ---- issue all 4 LDG.128s back-to-back (MLP=4) ----
    float4 v0 = xp[t];
    float4 v1 = xp[t + 256];
    float4 v2 = xp[t + 512];
    float4 v3 = xp[t + 768];

    // ---- weights while loads are in flight ----
    // Per thread: x = (4t)&63 (iteration-invariant, 16B-aligned -> LDS.128),
    //             y = (4t)>>6 + {0,16,32,48}.
    const int x  = (4 * t) & 63;
    const int y0 = (4 * t) >> 6;
    float4 gxv = *reinterpret_cast<const float4*>(&gx[x]);   // aligned LDS.128
    float gy0 = gy[y0];
    float gy1 = gy[y0 + 16];
    float gy2 = gy[y0 + 32];
    float gy3 = gy[y0 + 48];

    float acc;
    acc  = gy0 * (v0.x * gxv.x + v0.y * gxv.y + v0.z * gxv.z + v0.w * gxv.w);
    acc += gy1 * (v1.x * gxv.x + v1.y * gxv.y + v1.z * gxv.z + v1.w * gxv.w);
    acc += gy2 * (v2.x * gxv.x + v2.y * gxv.y + v2.z * gxv.z + v2.w * gxv.w);
    acc += gy3 * (v3.x * gxv.x + v3.y * gxv.y + v3.z * gxv.z + v3.w * gxv.w);

    // ---- reduction ----
    #pragma unroll
    for (int off = 16; off > 0; off >>= 1)
        acc += __shfl_down_sync(0xffffffffu, acc, off);

    if ((t & 31) == 0) red[t >> 5] = acc;
    __syncthreads();

    if (t < 8) {
        float v = red[t];
        #pragma unroll
        for (int off = 4; off > 0; off >>= 1)
            v += __shfl_down_sync(0x000000ffu, v, off);
        if (t == 0) out[blk] = v;
    }
}

extern "C" void kernel_launch(void* const* d_in, const int* in_sizes, int n_in,
                              void* d_out, int out_size) {
    // metadata order: X, wx, wy, wsigmax, wsigmay, mask
    const float* X   = (const float*)d_in[0];
    const float* wx  = (const float*)d_in[1];
    const float* wy  = (const float*)d_in[2];
    const float* wsx = (const float*)d_in[3];
    const float* wsy = (const float*)d_in[4];
    // mask (d_in[5]) is all-true by construction; nonzero(size=C) gather is identity.
    float* out = (float*)d_out;

    const int B = in_sizes[0] / (NCH * HH * WW);   // 32
    const int nblocks = B * NCH;                   // 32768

    gaussian_sampler_kernel<<<nblocks, 256>>>(X, wx, wy, wsx, wsy, out);
}